// round 1
// baseline (speedup 1.0000x reference)
#include <cuda_runtime.h>
#include <cuda_bf16.h>
#include <math.h>

#define NROWS 10000
#define S_    20
#define D_    512
#define DOUT_ 512
#define ATTEN_ 64
#define D4_   (D_/4)   // 128

// Scratch (device globals -- no allocations allowed)
__device__ float g_neigh_sum[NROWS * D_];
__device__ float g_from_self[NROWS * DOUT_];
__device__ float g_from_neighs[NROWS * DOUT_];
__device__ float g_self_ai[NROWS * ATTEN_];
__device__ float g_neigh_ai[NROWS * ATTEN_];

// ---------------------------------------------------------------------------
// Kernel 1: per-row neighbor softmax + weighted reduction over S
// grid = NROWS, block = 128 (one float4 of D per thread)
// ---------------------------------------------------------------------------
__global__ void reduce_kernel(const float* __restrict__ neigh_vecs,
                              const float* __restrict__ neigh_weight,
                              const int*   __restrict__ neigh_column,
                              const float* __restrict__ alpha,
                              float*       __restrict__ neigh_sum) {
    int n   = blockIdx.x;
    int tid = threadIdx.x;

    __shared__ float aexp[S_];
    __shared__ float w[S_];
    __shared__ float inv_sum;

    if (tid < S_) {
        int col = neigh_column[n * S_ + tid];
        aexp[tid] = expf(alpha[col]);
    }
    __syncthreads();
    if (tid == 0) {
        float s = 0.f;
        #pragma unroll
        for (int i = 0; i < S_; i++) s += aexp[i];
        inv_sum = 1.f / s;
    }
    __syncthreads();
    if (tid < S_) {
        w[tid] = neigh_weight[n * S_ + tid] * aexp[tid] * inv_sum;
    }
    __syncthreads();

    const float4* nv = reinterpret_cast<const float4*>(neigh_vecs) + (size_t)n * S_ * D4_;
    float4 acc = make_float4(0.f, 0.f, 0.f, 0.f);
    #pragma unroll
    for (int s = 0; s < S_; s++) {
        float4 x = nv[s * D4_ + tid];
        float ws = w[s];
        acc.x = fmaf(x.x, ws, acc.x);
        acc.y = fmaf(x.y, ws, acc.y);
        acc.z = fmaf(x.z, ws, acc.z);
        acc.w = fmaf(x.w, ws, acc.w);
    }
    reinterpret_cast<float4*>(neigh_sum)[(size_t)n * D4_ + tid] = acc;
}

// ---------------------------------------------------------------------------
// Kernel 2: tiled fp32 GEMM  C[M,Nc] = A[M,K] @ B[K,Nc]
// BM=BN=64, BK=16, 256 threads, 4x4 per thread, float4 smem reads.
// K divisible by 16, Nc divisible by 64; M edge predicated.
// ---------------------------------------------------------------------------
__global__ void gemm64(const float* __restrict__ A,
                       const float* __restrict__ B,
                       float*       __restrict__ C,
                       int M, int K, int Nc) {
    const int BM = 64, BN = 64, BK = 16;
    __shared__ float As[BK][BM];   // transposed: As[k][m]
    __shared__ float Bs[BK][BN];

    int tid  = threadIdx.x;            // 0..255
    int row0 = blockIdx.y * BM;
    int col0 = blockIdx.x * BN;

    int tx = tid % 16;                 // col group
    int ty = tid / 16;                 // row group

    // load indices
    int la_row = tid / 4;              // 0..63
    int la_col = (tid % 4) * 4;        // 0,4,8,12
    int lb_row = tid / 16;             // 0..15
    int lb_col = (tid % 16) * 4;       // 0..60

    float acc[4][4];
    #pragma unroll
    for (int i = 0; i < 4; i++)
        #pragma unroll
        for (int j = 0; j < 4; j++) acc[i][j] = 0.f;

    int ar = row0 + la_row;
    bool a_ok = (ar < M);

    for (int k0 = 0; k0 < K; k0 += BK) {
        float4 av = make_float4(0.f, 0.f, 0.f, 0.f);
        if (a_ok) av = *reinterpret_cast<const float4*>(&A[(size_t)ar * K + k0 + la_col]);
        As[la_col + 0][la_row] = av.x;
        As[la_col + 1][la_row] = av.y;
        As[la_col + 2][la_row] = av.z;
        As[la_col + 3][la_row] = av.w;

        float4 bv = *reinterpret_cast<const float4*>(&B[(size_t)(k0 + lb_row) * Nc + col0 + lb_col]);
        *reinterpret_cast<float4*>(&Bs[lb_row][lb_col]) = bv;
        __syncthreads();

        #pragma unroll
        for (int kk = 0; kk < BK; kk++) {
            float4 a4 = *reinterpret_cast<const float4*>(&As[kk][ty * 4]);
            float4 b4 = *reinterpret_cast<const float4*>(&Bs[kk][tx * 4]);
            float a[4] = {a4.x, a4.y, a4.z, a4.w};
            float b[4] = {b4.x, b4.y, b4.z, b4.w};
            #pragma unroll
            for (int i = 0; i < 4; i++)
                #pragma unroll
                for (int j = 0; j < 4; j++)
                    acc[i][j] = fmaf(a[i], b[j], acc[i][j]);
        }
        __syncthreads();
    }

    #pragma unroll
    for (int i = 0; i < 4; i++) {
        int r = row0 + ty * 4 + i;
        if (r < M) {
            float4 o = make_float4(acc[i][0], acc[i][1], acc[i][2], acc[i][3]);
            *reinterpret_cast<float4*>(&C[(size_t)r * Nc + col0 + tx * 4]) = o;
        }
    }
}

// ---------------------------------------------------------------------------
// Kernel 3: gating epilogue. One warp per row.
// ---------------------------------------------------------------------------
__global__ void epilogue_kernel(const float* __restrict__ from_self,
                                const float* __restrict__ from_neighs,
                                const float* __restrict__ self_ai,
                                const float* __restrict__ neigh_ai,
                                const float* __restrict__ v,
                                float*       __restrict__ out) {
    int warp = (blockIdx.x * blockDim.x + threadIdx.x) >> 5;
    int lane = threadIdx.x & 31;
    if (warp >= NROWS) return;

    float s1 = 0.f, s2 = 0.f;
    #pragma unroll
    for (int i = lane; i < ATTEN_; i += 32) {
        float vi = v[i];
        float sa = self_ai[(size_t)warp * ATTEN_ + i];
        float na = neigh_ai[(size_t)warp * ATTEN_ + i];
        s1 = fmaf(sa + sa, vi, s1);
        s2 = fmaf(na + sa, vi, s2);
    }
    #pragma unroll
    for (int o = 16; o > 0; o >>= 1) {
        s1 += __shfl_xor_sync(0xFFFFFFFFu, s1, o);
        s2 += __shfl_xor_sync(0xFFFFFFFFu, s2, o);
    }
    float a_s = expf(tanhf(s1));
    float a_n = expf(tanhf(s2));
    float inv = 1.f / (a_s + a_n);
    float gs = a_s * inv;
    float gn = a_n * inv;

    const float4* fs = reinterpret_cast<const float4*>(from_self)   + (size_t)warp * (DOUT_/4);
    const float4* fn = reinterpret_cast<const float4*>(from_neighs) + (size_t)warp * (DOUT_/4);
    float4*       po = reinterpret_cast<float4*>(out)               + (size_t)warp * (DOUT_/4);
    #pragma unroll 4
    for (int d = lane; d < DOUT_/4; d += 32) {
        float4 x = fs[d];
        float4 y = fn[d];
        float4 r;
        r.x = fmaxf(fmaf(gs, x.x, gn * y.x), 0.f);
        r.y = fmaxf(fmaf(gs, x.y, gn * y.y), 0.f);
        r.z = fmaxf(fmaf(gs, x.z, gn * y.z), 0.f);
        r.w = fmaxf(fmaf(gs, x.w, gn * y.w), 0.f);
        po[d] = r;
    }
}

// ---------------------------------------------------------------------------
extern "C" void kernel_launch(void* const* d_in, const int* in_sizes, int n_in,
                              void* d_out, int out_size) {
    const float* self_vecs     = (const float*)d_in[0];
    const float* neigh_vecs    = (const float*)d_in[1];
    const float* neigh_weight  = (const float*)d_in[2];
    const int*   neigh_column  = (const int*)  d_in[3];
    const float* neigh_weights = (const float*)d_in[4];
    const float* self_weights  = (const float*)d_in[5];
    const float* alpha         = (const float*)d_in[6];
    const float* self_atten    = (const float*)d_in[7];
    const float* neigh_atten   = (const float*)d_in[8];
    const float* v             = (const float*)d_in[9];
    float* out = (float*)d_out;

    float *p_nsum, *p_fs, *p_fn, *p_sai, *p_nai;
    cudaGetSymbolAddress((void**)&p_nsum, g_neigh_sum);
    cudaGetSymbolAddress((void**)&p_fs,   g_from_self);
    cudaGetSymbolAddress((void**)&p_fn,   g_from_neighs);
    cudaGetSymbolAddress((void**)&p_sai,  g_self_ai);
    cudaGetSymbolAddress((void**)&p_nai,  g_neigh_ai);

    // 1. neighbor softmax + reduce
    reduce_kernel<<<NROWS, 128>>>(neigh_vecs, neigh_weight, neigh_column, alpha, p_nsum);

    // 2. four GEMMs
    dim3 blk(256);
    int mblocks = (NROWS + 63) / 64;
    gemm64<<<dim3(DOUT_/64, mblocks), blk>>>(self_vecs, self_weights, p_fs, NROWS, D_, DOUT_);
    gemm64<<<dim3(DOUT_/64, mblocks), blk>>>(p_nsum,    neigh_weights, p_fn, NROWS, D_, DOUT_);
    gemm64<<<dim3(ATTEN_/64, mblocks), blk>>>(self_vecs, self_atten,  p_sai, NROWS, D_, ATTEN_);
    gemm64<<<dim3(ATTEN_/64, mblocks), blk>>>(p_nsum,    neigh_atten, p_nai, NROWS, D_, ATTEN_);

    // 3. gate + blend + relu
    int threads = 256;
    int warps_per_block = threads / 32;
    int blocks = (NROWS + warps_per_block - 1) / warps_per_block;
    epilogue_kernel<<<blocks, threads>>>(p_fs, p_fn, p_sai, p_nai, v, out);
}

// round 3
// speedup vs baseline: 3.2494x; 3.2494x over previous
#include <cuda_runtime.h>
#include <cuda_bf16.h>
#include <cstdint>
#include <math.h>

#define NROWS 10000
#define S_    20
#define D_    512
#define DOUT_ 512
#define ATTEN_ 64
#define D4_   (D_/4)

// ---------------------------------------------------------------------------
// Scratch (device globals -- no allocations allowed)
// ---------------------------------------------------------------------------
__device__ float g_neigh_sum[NROWS * D_];
__device__ float g_from_self[NROWS * DOUT_];
__device__ float g_from_neighs[NROWS * DOUT_];
__device__ float g_self_ai[NROWS * ATTEN_];
__device__ float g_neigh_ai[NROWS * ATTEN_];

// ---------------------------------------------------------------------------
// bf16 split helpers: x = hi + lo with ~16-bit combined mantissa.
// pack(a,b) puts a in low 16 bits (element k), b in high (element k+1).
// ---------------------------------------------------------------------------
__device__ __forceinline__ void split2(float a, float b, uint32_t& hi, uint32_t& lo) {
    __nv_bfloat162 h = __floats2bfloat162_rn(a, b);
    float2 hf = __bfloat1622float2(h);
    __nv_bfloat162 l = __floats2bfloat162_rn(a - hf.x, b - hf.y);
    hi = *reinterpret_cast<uint32_t*>(&h);
    lo = *reinterpret_cast<uint32_t*>(&l);
}

__device__ __forceinline__ void mma16816(float* c, const uint32_t* a, const uint32_t* b) {
    asm volatile(
        "mma.sync.aligned.m16n8k16.row.col.f32.bf16.bf16.f32 "
        "{%0,%1,%2,%3}, {%4,%5,%6,%7}, {%8,%9}, {%0,%1,%2,%3};"
        : "+f"(c[0]), "+f"(c[1]), "+f"(c[2]), "+f"(c[3])
        : "r"(a[0]), "r"(a[1]), "r"(a[2]), "r"(a[3]), "r"(b[0]), "r"(b[1]));
}

// ---------------------------------------------------------------------------
// Kernel 1: per-row neighbor softmax + weighted reduction over S
// ---------------------------------------------------------------------------
__global__ void reduce_kernel(const float* __restrict__ neigh_vecs,
                              const float* __restrict__ neigh_weight,
                              const int*   __restrict__ neigh_column,
                              const float* __restrict__ alpha,
                              float*       __restrict__ neigh_sum) {
    int n   = blockIdx.x;
    int tid = threadIdx.x;

    __shared__ float aexp[S_];
    __shared__ float w[S_];
    __shared__ float inv_sum;

    if (tid < S_) {
        int col = neigh_column[n * S_ + tid];
        aexp[tid] = expf(alpha[col]);
    }
    __syncthreads();
    if (tid == 0) {
        float s = 0.f;
        #pragma unroll
        for (int i = 0; i < S_; i++) s += aexp[i];
        inv_sum = 1.f / s;
    }
    __syncthreads();
    if (tid < S_) w[tid] = neigh_weight[n * S_ + tid] * aexp[tid] * inv_sum;
    __syncthreads();

    const float4* nv = reinterpret_cast<const float4*>(neigh_vecs) + (size_t)n * S_ * D4_;
    float4 acc = make_float4(0.f, 0.f, 0.f, 0.f);
    #pragma unroll
    for (int s = 0; s < S_; s++) {
        float4 x = nv[s * D4_ + tid];
        float ws = w[s];
        acc.x = fmaf(x.x, ws, acc.x);
        acc.y = fmaf(x.y, ws, acc.y);
        acc.z = fmaf(x.z, ws, acc.z);
        acc.w = fmaf(x.w, ws, acc.w);
    }
    reinterpret_cast<float4*>(neigh_sum)[(size_t)n * D4_ + tid] = acc;
}

// ---------------------------------------------------------------------------
// Kernel 2: bf16-split tensor GEMM via mma.sync m16n8k16.
//   C[M,Nw] = A[M,512] @ W[512,Nw], fp32 in/out, 3 bf16 chains (hh, hl, lh).
// Block tile 128 x BN, BK=32, 8 warps (warp tile 32 x BN/2).
// blockIdx.z selects one of two independent (A,W,C) problems.
// ---------------------------------------------------------------------------
template<int BN>
__global__ void __launch_bounds__(256, 1)
gemm_mma(const float* __restrict__ A0, const float* __restrict__ W0, float* __restrict__ C0,
         const float* __restrict__ A1, const float* __restrict__ W1, float* __restrict__ C1,
         int M, int Nw) {
    constexpr int K       = 512;
    constexpr int BK      = 32;
    constexpr int NITER   = K / BK;            // 16
    constexpr int ASTRIDE = 20;                // u32 per A row (16 pairs + 4 pad)
    constexpr int APART   = 128 * ASTRIDE;     // 2560 u32
    constexpr int BSTRIDE = BN + 8;            // u32 per B k2-row
    constexpr int BPART   = 16 * BSTRIDE;      // u32
    constexpr int STG     = 2 * APART + 2 * BPART;
    constexpr int WN      = BN / 2;            // warp n extent
    constexpr int WNT     = WN / 8;            // n tiles per warp
    constexpr int BSLOT   = (16 * (BN / 4)) / 256;  // B float4-pairs per thread

    const float* A = blockIdx.z ? A1 : A0;
    const float* W = blockIdx.z ? W1 : W0;
    float*       C = blockIdx.z ? C1 : C0;

    extern __shared__ uint32_t s32[];

    int tid  = threadIdx.x;
    int wid  = tid >> 5, lane = tid & 31;
    int wm   = wid & 3, wn = wid >> 2;         // warp grid 4 (m) x 2 (n)
    int m0   = blockIdx.y * 128;
    int n0   = blockIdx.x * BN;

    float acc[2][WNT][4];
    #pragma unroll
    for (int i = 0; i < 2; i++)
        #pragma unroll
        for (int j = 0; j < WNT; j++)
            #pragma unroll
            for (int e = 0; e < 4; e++) acc[i][j][e] = 0.f;

    float4 areg[4];
    float4 b0reg[BSLOT], b1reg[BSLOT];

    auto load_gmem = [&](int ic) {
        int k0 = ic * BK;
        #pragma unroll
        for (int j = 0; j < 4; j++) {
            int s = tid + j * 256;
            int m = s >> 3, k4 = s & 7;
            areg[j] = (m0 + m < M)
                ? *reinterpret_cast<const float4*>(&A[(size_t)(m0 + m) * K + k0 + k4 * 4])
                : make_float4(0.f, 0.f, 0.f, 0.f);
        }
        #pragma unroll
        for (int j = 0; j < BSLOT; j++) {
            int s = tid + j * 256;
            int k2 = s / (BN / 4), n4 = s % (BN / 4);
            b0reg[j] = *reinterpret_cast<const float4*>(&W[(size_t)(k0 + 2 * k2    ) * Nw + n0 + n4 * 4]);
            b1reg[j] = *reinterpret_cast<const float4*>(&W[(size_t)(k0 + 2 * k2 + 1) * Nw + n0 + n4 * 4]);
        }
    };

    auto store_smem = [&](int p) {
        uint32_t* AH = s32 + p * STG;
        uint32_t* AL = AH + APART;
        uint32_t* BH = AL + APART;
        uint32_t* BL = BH + BPART;
        #pragma unroll
        for (int j = 0; j < 4; j++) {
            int s = tid + j * 256;
            int m = s >> 3, k2 = (s & 7) * 2;
            uint32_t h0, l0, h1, l1;
            split2(areg[j].x, areg[j].y, h0, l0);
            split2(areg[j].z, areg[j].w, h1, l1);
            AH[m * ASTRIDE + k2]     = h0;
            AH[m * ASTRIDE + k2 + 1] = h1;
            AL[m * ASTRIDE + k2]     = l0;
            AL[m * ASTRIDE + k2 + 1] = l1;
        }
        #pragma unroll
        for (int j = 0; j < BSLOT; j++) {
            int s = tid + j * 256;
            int k2 = s / (BN / 4), n4 = s % (BN / 4);
            uint32_t ph[4], pl[4];
            split2(b0reg[j].x, b1reg[j].x, ph[0], pl[0]);
            split2(b0reg[j].y, b1reg[j].y, ph[1], pl[1]);
            split2(b0reg[j].z, b1reg[j].z, ph[2], pl[2]);
            split2(b0reg[j].w, b1reg[j].w, ph[3], pl[3]);
            *reinterpret_cast<uint4*>(&BH[k2 * BSTRIDE + n4 * 4]) = make_uint4(ph[0], ph[1], ph[2], ph[3]);
            *reinterpret_cast<uint4*>(&BL[k2 * BSTRIDE + n4 * 4]) = make_uint4(pl[0], pl[1], pl[2], pl[3]);
        }
    };

    auto compute = [&](int p) {
        const uint32_t* AH = s32 + p * STG;
        const uint32_t* AL = AH + APART;
        const uint32_t* BH = AL + APART;
        const uint32_t* BL = BH + BPART;
        #pragma unroll
        for (int ch = 0; ch < 3; ch++) {
            const uint32_t* Ax = (ch == 2) ? AL : AH;
            const uint32_t* Bx = (ch == 1) ? BL : BH;
            #pragma unroll
            for (int ks = 0; ks < 2; ks++) {
                int base8 = ks * 8;
                uint32_t af[2][4];
                #pragma unroll
                for (int mt = 0; mt < 2; mt++) {
                    int row = wm * 32 + mt * 16 + (lane >> 2);
                    int kc  = base8 + (lane & 3);
                    af[mt][0] = Ax[row * ASTRIDE + kc];
                    af[mt][1] = Ax[(row + 8) * ASTRIDE + kc];
                    af[mt][2] = Ax[row * ASTRIDE + kc + 4];
                    af[mt][3] = Ax[(row + 8) * ASTRIDE + kc + 4];
                }
                uint32_t bf[WNT][2];
                #pragma unroll
                for (int nt = 0; nt < WNT; nt++) {
                    int col = wn * WN + nt * 8 + (lane >> 2);
                    int kc  = base8 + (lane & 3);
                    bf[nt][0] = Bx[kc * BSTRIDE + col];
                    bf[nt][1] = Bx[(kc + 4) * BSTRIDE + col];
                }
                #pragma unroll
                for (int mt = 0; mt < 2; mt++)
                    #pragma unroll
                    for (int nt = 0; nt < WNT; nt++)
                        mma16816(acc[mt][nt], af[mt], bf[nt]);
            }
        }
    };

    // pipeline: regs(k+1) in flight while computing k; one sync per iter
    load_gmem(0);
    store_smem(0);
    __syncthreads();
    for (int ic = 0; ic < NITER; ic++) {
        if (ic + 1 < NITER) load_gmem(ic + 1);
        compute(ic & 1);
        if (ic + 1 < NITER) store_smem((ic + 1) & 1);
        __syncthreads();
    }

    // epilogue: direct float2 stores
    #pragma unroll
    for (int mt = 0; mt < 2; mt++) {
        #pragma unroll
        for (int nt = 0; nt < WNT; nt++) {
            int row = m0 + wm * 32 + mt * 16 + (lane >> 2);
            int col = n0 + wn * WN + nt * 8 + (lane & 3) * 2;
            if (row < M)
                *reinterpret_cast<float2*>(&C[(size_t)row * Nw + col]) =
                    make_float2(acc[mt][nt][0], acc[mt][nt][1]);
            if (row + 8 < M)
                *reinterpret_cast<float2*>(&C[(size_t)(row + 8) * Nw + col]) =
                    make_float2(acc[mt][nt][2], acc[mt][nt][3]);
        }
    }
}

// ---------------------------------------------------------------------------
// Kernel 3: gating epilogue. One warp per row.
// ---------------------------------------------------------------------------
__global__ void epilogue_kernel(const float* __restrict__ from_self,
                                const float* __restrict__ from_neighs,
                                const float* __restrict__ self_ai,
                                const float* __restrict__ neigh_ai,
                                const float* __restrict__ v,
                                float*       __restrict__ out) {
    int warp = (blockIdx.x * blockDim.x + threadIdx.x) >> 5;
    int lane = threadIdx.x & 31;
    if (warp >= NROWS) return;

    float s1 = 0.f, s2 = 0.f;
    #pragma unroll
    for (int i = lane; i < ATTEN_; i += 32) {
        float vi = v[i];
        float sa = self_ai[(size_t)warp * ATTEN_ + i];
        float na = neigh_ai[(size_t)warp * ATTEN_ + i];
        s1 = fmaf(sa + sa, vi, s1);
        s2 = fmaf(na + sa, vi, s2);
    }
    #pragma unroll
    for (int o = 16; o > 0; o >>= 1) {
        s1 += __shfl_xor_sync(0xFFFFFFFFu, s1, o);
        s2 += __shfl_xor_sync(0xFFFFFFFFu, s2, o);
    }
    float a_s = expf(tanhf(s1));
    float a_n = expf(tanhf(s2));
    float inv = 1.f / (a_s + a_n);
    float gs = a_s * inv;
    float gn = a_n * inv;

    const float4* fs = reinterpret_cast<const float4*>(from_self)   + (size_t)warp * (DOUT_/4);
    const float4* fn = reinterpret_cast<const float4*>(from_neighs) + (size_t)warp * (DOUT_/4);
    float4*       po = reinterpret_cast<float4*>(out)               + (size_t)warp * (DOUT_/4);
    #pragma unroll 4
    for (int d = lane; d < DOUT_/4; d += 32) {
        float4 x = fs[d];
        float4 y = fn[d];
        float4 r;
        r.x = fmaxf(fmaf(gs, x.x, gn * y.x), 0.f);
        r.y = fmaxf(fmaf(gs, x.y, gn * y.y), 0.f);
        r.z = fmaxf(fmaf(gs, x.z, gn * y.z), 0.f);
        r.w = fmaxf(fmaf(gs, x.w, gn * y.w), 0.f);
        po[d] = r;
    }
}

// ---------------------------------------------------------------------------
extern "C" void kernel_launch(void* const* d_in, const int* in_sizes, int n_in,
                              void* d_out, int out_size) {
    const float* self_vecs     = (const float*)d_in[0];
    const float* neigh_vecs    = (const float*)d_in[1];
    const float* neigh_weight  = (const float*)d_in[2];
    const int*   neigh_column  = (const int*)  d_in[3];
    const float* neigh_weights = (const float*)d_in[4];
    const float* self_weights  = (const float*)d_in[5];
    const float* alpha         = (const float*)d_in[6];
    const float* self_atten    = (const float*)d_in[7];
    const float* neigh_atten   = (const float*)d_in[8];
    const float* v             = (const float*)d_in[9];
    float* out = (float*)d_out;

    float *p_nsum, *p_fs, *p_fn, *p_sai, *p_nai;
    cudaGetSymbolAddress((void**)&p_nsum, g_neigh_sum);
    cudaGetSymbolAddress((void**)&p_fs,   g_from_self);
    cudaGetSymbolAddress((void**)&p_fn,   g_from_neighs);
    cudaGetSymbolAddress((void**)&p_sai,  g_self_ai);
    cudaGetSymbolAddress((void**)&p_nai,  g_neigh_ai);

    // smem sizes (bytes): STG u32 per stage * 2 stages * 4
    const int SMEM128 = 2 * (2 * 128 * 20 + 2 * 16 * (128 + 8)) * 4;  // 75776
    const int SMEM64  = 2 * (2 * 128 * 20 + 2 * 16 * ( 64 + 8)) * 4;  // 59392
    cudaFuncSetAttribute(gemm_mma<128>, cudaFuncAttributeMaxDynamicSharedMemorySize, SMEM128);
    cudaFuncSetAttribute(gemm_mma<64>,  cudaFuncAttributeMaxDynamicSharedMemorySize, SMEM64);

    // 1. neighbor softmax + reduce
    reduce_kernel<<<NROWS, 128>>>(neigh_vecs, neigh_weight, neigh_column, alpha, p_nsum);

    // 2. tensor GEMMs (z fuses the two independent problems per shape)
    int mblocks = (NROWS + 127) / 128;   // 79
    gemm_mma<128><<<dim3(DOUT_/128, mblocks, 2), 256, SMEM128>>>(
        self_vecs, self_weights, p_fs,
        p_nsum,    neigh_weights, p_fn, NROWS, DOUT_);
    gemm_mma<64><<<dim3(1, mblocks, 2), 256, SMEM64>>>(
        self_vecs, self_atten,  p_sai,
        p_nsum,    neigh_atten, p_nai, NROWS, ATTEN_);

    // 3. gate + blend + relu
    int threads = 256;
    int blocks = (NROWS + (threads / 32) - 1) / (threads / 32);
    epilogue_kernel<<<blocks, threads>>>(p_fs, p_fn, p_sai, p_nai, v, out);
}